// round 9
// baseline (speedup 1.0000x reference)
#include <cuda_runtime.h>
#include <cuda_bf16.h>

// Problem constants: B=2048, T=512, I=4, H=64, O=4
#define TT 512
#define BB 2048
#define HH 64
#define OO 4
#define NB 7     // batch rows per block
#define GRID 296 // 2 blocks per SM on 148 SMs
#define NT 128   // threads per block

// ---- packed fp32x2 ops (Blackwell) ----
__device__ __forceinline__ void fma2(unsigned long long &a, unsigned long long w, unsigned long long h){
    asm("fma.rn.f32x2 %0, %1, %2, %0;" : "+l"(a) : "l"(w), "l"(h));
}
__device__ __forceinline__ unsigned long long add2(unsigned long long a, unsigned long long b){
    unsigned long long r; asm("add.rn.f32x2 %0, %1, %2;" : "=l"(r) : "l"(a), "l"(b)); return r;
}
__device__ __forceinline__ float2 unpack2(unsigned long long v){
    float2 r; asm("mov.b64 {%0, %1}, %2;" : "=f"(r.x), "=f"(r.y) : "l"(v)); return r;
}
__device__ __forceinline__ unsigned long long pack2(float lo, float hi){
    unsigned long long r; asm("mov.b64 %0, {%1, %2};" : "=l"(r) : "f"(lo), "f"(hi)); return r;
}
// ---- native MUFU tanh + sigmoid via tanh ----
__device__ __forceinline__ float tanh_ap(float x){
    float r; asm("tanh.approx.f32 %0, %1;" : "=f"(r) : "f"(x)); return r;
}
__device__ __forceinline__ float sig_ap(float x){
    return __fmaf_rn(0.5f, tanh_ap(0.5f * x), 0.5f);
}

__global__ void __launch_bounds__(NT, 2) lstm_fused_kernel(
    const float* __restrict__ x,     // [B, T, I]
    const float* __restrict__ W_ih,  // [4H, I]
    const float* __restrict__ W_hh,  // [4H, H]
    const float* __restrict__ b_ih,  // [4H]
    const float* __restrict__ b_hh,  // [4H]
    const float* __restrict__ W_fc,  // [O, H]
    const float* __restrict__ b_fc,  // [O]
    float* __restrict__ out)         // [1, B, O]
{
    __shared__ __align__(16) float h_sh[2][NB][HH];  // DOUBLE-BUFFERED hidden state
    __shared__ __align__(16) float4 x_sh[2][NB];     // double-buffered x_t

    const int tid   = threadIdx.x;
    const int role  = tid & 1;                       // 0: (i,g) rows; 1: (f,o) rows
    const int hown  = tid >> 1;                      // hidden unit owned by this lane pair
    const int row0  = role * 64 + hown;              // i (role0) / f (role1)
    const int row1  = row0 + 128;                    // g (role0) / o (role1)
    const int bbase = blockIdx.x * NB;

    // Two W_hh rows in registers: 2 x 32 packed fp32 pairs (128 regs)
    unsigned long long wA[32], wB[32];
    {
        const unsigned long long* wpA = (const unsigned long long*)(W_hh + (size_t)row0 * HH);
        const unsigned long long* wpB = (const unsigned long long*)(W_hh + (size_t)row1 * HH);
        #pragma unroll
        for (int j = 0; j < 32; j++){ wA[j] = wpA[j]; wB[j] = wpB[j]; }
    }
    const unsigned long long wihA01 = pack2(W_ih[row0*4 + 0], W_ih[row0*4 + 1]);
    const unsigned long long wihA23 = pack2(W_ih[row0*4 + 2], W_ih[row0*4 + 3]);
    const unsigned long long wihB01 = pack2(W_ih[row1*4 + 0], W_ih[row1*4 + 1]);
    const unsigned long long wihB23 = pack2(W_ih[row1*4 + 2], W_ih[row1*4 + 3]);
    const unsigned long long biasA  = pack2(b_ih[row0] + b_hh[row0], 0.f);
    const unsigned long long biasB  = pack2(b_ih[row1] + b_hh[row1], 0.f);

    // Activation folding constants for row1: role0 -> tanh(x)=cm*tanh(cm*x)+ca with cm=1,ca=0
    //                                        role1 -> sigmoid(x)=0.5*tanh(0.5*x)+0.5
    const float cm = role ? 0.5f : 1.0f;
    const float ca = role ? 0.5f : 0.0f;

    // Cell state: role1 lane holds c for its hidden unit across all NB batches.
    float c[NB];
    #pragma unroll
    for (int b = 0; b < NB; b++) c[b] = 0.f;

    // init h buffer 0 = 0; zero x_sh; preload x for t=0
    for (int i = tid; i < 2 * NB * HH; i += NT) ((float*)h_sh)[i] = 0.f;
    if (tid < 2 * NB) ((float4*)x_sh)[tid] = make_float4(0.f, 0.f, 0.f, 0.f);
    __syncthreads();
    if (tid < NB && (bbase + tid) < BB)
        x_sh[0][tid] = ((const float4*)x)[ (size_t)(bbase + tid) * TT ];
    __syncthreads();

    for (int t = 0; t < TT; t++){
        // prefetch next x (latency hidden under GEMV)
        float4 xnext;
        const bool pre = (tid < NB) && (t + 1 < TT) && ((bbase + tid) < BB);
        if (pre) xnext = ((const float4*)x)[ (size_t)(bbase + tid) * TT + (t + 1) ];

        const float (*hc)[HH] = h_sh[t & 1];          // read buffer
        float (*hn)[HH]       = h_sh[(t + 1) & 1];    // write buffer
        const ulonglong2* xcur = (const ulonglong2*)x_sh[t & 1];

        // ---- per batch: GEMV (2 rows) + in-register activation + pairwise cell ----
        #pragma unroll
        for (int b = 0; b < NB; b++){
            const ulonglong2* hp = (const ulonglong2*)hc[b];   // broadcast LDS.128
            ulonglong2 xv = xcur[b];
            unsigned long long aA0 = biasA, aA1 = 0ull, aA2 = 0ull, aA3 = 0ull;
            unsigned long long aB0 = biasB, aB1 = 0ull, aB2 = 0ull, aB3 = 0ull;
            fma2(aA0, wihA01, xv.x);  fma2(aA1, wihA23, xv.y);
            fma2(aB0, wihB01, xv.x);  fma2(aB1, wihB23, xv.y);
            #pragma unroll
            for (int j = 0; j < 8; j++){
                ulonglong2 hv0 = hp[2*j];
                ulonglong2 hv1 = hp[2*j + 1];
                fma2(aA0, wA[4*j + 0], hv0.x);
                fma2(aA1, wA[4*j + 1], hv0.y);
                fma2(aA2, wA[4*j + 2], hv1.x);
                fma2(aA3, wA[4*j + 3], hv1.y);
                fma2(aB0, wB[4*j + 0], hv0.x);
                fma2(aB1, wB[4*j + 1], hv0.y);
                fma2(aB2, wB[4*j + 2], hv1.x);
                fma2(aB3, wB[4*j + 3], hv1.y);
            }
            float2 fA = unpack2(add2(add2(aA0, aA1), add2(aA2, aA3)));
            float2 fB = unpack2(add2(add2(aB0, aB1), add2(aB2, aB3)));
            float sumA = fA.x + fA.y;                 // i (role0) / f (role1)
            float sumB = fB.x + fB.y;                 // g (role0) / o (role1)

            // activations (uniform code, no divergence)
            float act0 = sig_ap(sumA);                // sig(i) / sig(f)
            float tv   = tanh_ap(cm * sumB);
            float act1 = __fmaf_rn(cm, tv, ca);       // tanh(g) / sig(o)

            // pair exchange: role0 sends sig(i)*tanh(g); role1 sends junk (unused)
            float p = act0 * act1;
            float q = __shfl_xor_sync(0xffffffffu, p, 1);

            // cell update (meaningful on role1 lanes; role0 computes bounded junk)
            c[b] = __fmaf_rn(act0, c[b], q);          // sig(f)*c + sig(i)*tanh(g)
            float hv = act1 * tanh_ap(c[b]);          // sig(o)*tanh(c)
            if (role) hn[b][hown] = hv;
        }
        if (pre) x_sh[(t + 1) & 1][tid] = xnext;
        __syncthreads();
    }

    // ---- FC head: final h is in buffer TT&1 == 0 ----
    if (tid < NB * OO){
        const int b = tid >> 2, o = tid & 3;
        if ((bbase + b) < BB){
            float s = b_fc[o];
            #pragma unroll
            for (int k = 0; k < HH; k++)
                s = __fmaf_rn(W_fc[o*HH + k], h_sh[0][b][k], s);
            out[(size_t)(bbase + b) * OO + o] = s;
        }
    }
}

extern "C" void kernel_launch(void* const* d_in, const int* in_sizes, int n_in,
                              void* d_out, int out_size)
{
    const float* x    = (const float*)d_in[0];
    const float* W_ih = (const float*)d_in[1];
    const float* W_hh = (const float*)d_in[2];
    const float* b_ih = (const float*)d_in[3];
    const float* b_hh = (const float*)d_in[4];
    const float* W_fc = (const float*)d_in[5];
    const float* b_fc = (const float*)d_in[6];
    float* out = (float*)d_out;

    lstm_fused_kernel<<<GRID, NT>>>(x, W_ih, W_hh, b_ih, b_hh, W_fc, b_fc, out);
}

// round 10
// speedup vs baseline: 1.1694x; 1.1694x over previous
#include <cuda_runtime.h>
#include <cuda_bf16.h>

// Problem constants: B=2048, T=512, I=4, H=64, O=4
#define TT 512
#define BB 2048
#define HH 64
#define GG 256   // 4*H gates
#define OO 4
#define NB 7     // batch rows per block
#define GRID 296 // 2 blocks per SM on 148 SMs
#define NT 128   // threads per block = gate pairs

// ---- packed fp32x2 ops (Blackwell) ----
__device__ __forceinline__ void fma2(unsigned long long &a, unsigned long long w, unsigned long long h){
    asm("fma.rn.f32x2 %0, %1, %2, %0;" : "+l"(a) : "l"(w), "l"(h));
}
__device__ __forceinline__ unsigned long long add2(unsigned long long a, unsigned long long b){
    unsigned long long r; asm("add.rn.f32x2 %0, %1, %2;" : "=l"(r) : "l"(a), "l"(b)); return r;
}
__device__ __forceinline__ float2 unpack2(unsigned long long v){
    float2 r; asm("mov.b64 {%0, %1}, %2;" : "=f"(r.x), "=f"(r.y) : "l"(v)); return r;
}
__device__ __forceinline__ unsigned long long pack2(float lo, float hi){
    unsigned long long r; asm("mov.b64 %0, {%1, %2};" : "=l"(r) : "f"(lo), "f"(hi)); return r;
}
// ---- native MUFU tanh + sigmoid via tanh ----
__device__ __forceinline__ float tanh_ap(float x){
    float r; asm("tanh.approx.f32 %0, %1;" : "=f"(r) : "f"(x)); return r;
}
__device__ __forceinline__ float sig_ap(float x){
    return __fmaf_rn(0.5f, tanh_ap(0.5f * x), 0.5f);
}

__global__ void __launch_bounds__(NT, 2) lstm_fused_kernel(
    const float* __restrict__ x,     // [B, T, I]
    const float* __restrict__ W_ih,  // [4H, I]
    const float* __restrict__ W_hh,  // [4H, H]
    const float* __restrict__ b_ih,  // [4H]
    const float* __restrict__ b_hh,  // [4H]
    const float* __restrict__ W_fc,  // [O, H]
    const float* __restrict__ b_fc,  // [O]
    float* __restrict__ out)         // [1, B, O]
{
    __shared__ __align__(16) float h_sh[NB][HH];     // hidden state
    __shared__ __align__(16) float g_sh[NB][GG];     // pre-activation gates
    __shared__ __align__(16) float4 x_sh[2][NB];     // double-buffered x_t

    const int tid   = threadIdx.x;                   // gate pair id in [0,128)
    const int g0    = tid;                           // first gate row
    const int g1    = tid + 128;                     // second gate row
    const int bbase = blockIdx.x * NB;

    // Two W_hh rows in registers: 2 x 32 packed fp32 pairs (128 regs)
    unsigned long long wA[32], wB[32];
    {
        const unsigned long long* wpA = (const unsigned long long*)(W_hh + (size_t)g0 * HH);
        const unsigned long long* wpB = (const unsigned long long*)(W_hh + (size_t)g1 * HH);
        #pragma unroll
        for (int j = 0; j < 32; j++){ wA[j] = wpA[j]; wB[j] = wpB[j]; }
    }
    const unsigned long long wihA01 = pack2(W_ih[g0*4 + 0], W_ih[g0*4 + 1]);
    const unsigned long long wihA23 = pack2(W_ih[g0*4 + 2], W_ih[g0*4 + 3]);
    const unsigned long long wihB01 = pack2(W_ih[g1*4 + 0], W_ih[g1*4 + 1]);
    const unsigned long long wihB23 = pack2(W_ih[g1*4 + 2], W_ih[g1*4 + 3]);
    const unsigned long long biasA  = pack2(b_ih[g0] + b_hh[g0], 0.f);
    const unsigned long long biasB  = pack2(b_ih[g1] + b_hh[g1], 0.f);

    // Cell update: 448 items over 128 threads: tid, tid+128, tid+256, tid+384 (tid<64)
    float c0 = 0.f, c1 = 0.f, c2 = 0.f, c3 = 0.f;

    // init h = 0; zero x_sh (OOB rows read zeros); preload x for t=0
    for (int i = tid; i < NB * HH; i += NT) ((float*)h_sh)[i] = 0.f;
    if (tid < 2 * NB) ((float4*)x_sh)[tid] = make_float4(0.f, 0.f, 0.f, 0.f);
    __syncthreads();
    if (tid < NB && (bbase + tid) < BB)
        x_sh[0][tid] = ((const float4*)x)[ (size_t)(bbase + tid) * TT ];
    __syncthreads();

    for (int t = 0; t < TT; t++){
        // prefetch next x (latency hidden under GEMV)
        float4 xnext;
        const bool pre = (tid < NB) && (t + 1 < TT) && ((bbase + tid) < BB);
        if (pre) xnext = ((const float4*)x)[ (size_t)(bbase + tid) * TT + (t + 1) ];

        const ulonglong2* xcur = (const ulonglong2*)x_sh[t & 1];

        // ---- gate GEMV: reuse-friendly ordering (A/B rows adjacent on same h),
        //      h loads software-pipelined one iteration ahead ----
        #pragma unroll
        for (int b = 0; b < NB; b++){
            const ulonglong2* hp = (const ulonglong2*)h_sh[b];   // broadcast LDS.128
            ulonglong2 xv = xcur[b];
            unsigned long long aA0 = biasA, aA1 = 0ull, aA2 = 0ull, aA3 = 0ull;
            unsigned long long aB0 = biasB, aB1 = 0ull, aB2 = 0ull, aB3 = 0ull;
            fma2(aA0, wihA01, xv.x);  fma2(aA1, wihA23, xv.y);
            fma2(aB0, wihB01, xv.x);  fma2(aB1, wihB23, xv.y);

            ulonglong2 hv0 = hp[0];
            ulonglong2 hv1 = hp[1];
            #pragma unroll
            for (int j = 0; j < 8; j++){
                ulonglong2 nhv0, nhv1;
                if (j < 7){ nhv0 = hp[2*j + 2]; nhv1 = hp[2*j + 3]; }
                // same h operand in consecutive instructions, same operand slot -> .reuse
                fma2(aA0, wA[4*j + 0], hv0.x);
                fma2(aB0, wB[4*j + 0], hv0.x);
                fma2(aA1, wA[4*j + 1], hv0.y);
                fma2(aB1, wB[4*j + 1], hv0.y);
                fma2(aA2, wA[4*j + 2], hv1.x);
                fma2(aB2, wB[4*j + 2], hv1.x);
                fma2(aA3, wA[4*j + 3], hv1.y);
                fma2(aB3, wB[4*j + 3], hv1.y);
                hv0 = nhv0; hv1 = nhv1;
            }
            float2 fA = unpack2(add2(add2(aA0, aA1), add2(aA2, aA3)));
            float2 fB = unpack2(add2(add2(aB0, aB1), add2(aB2, aB3)));
            g_sh[b][g0] = fA.x + fA.y;
            g_sh[b][g1] = fB.x + fB.y;
        }
        if (pre) x_sh[(t + 1) & 1][tid] = xnext;
        __syncthreads();

        // ---- LSTM cell update: 448 items, up to 4 per thread (gate order i,f,g,o) ----
        {
            {
                int b = tid >> 6, h = tid & 63;                       // b 0..1
                float gi = g_sh[b][h], gf = g_sh[b][HH+h], gg = g_sh[b][2*HH+h], go = g_sh[b][3*HH+h];
                c0 = sig_ap(gf) * c0 + sig_ap(gi) * tanh_ap(gg);
                h_sh[b][h] = sig_ap(go) * tanh_ap(c0);
            }
            {
                int i = tid + 128, b = i >> 6, h = i & 63;            // b 2..3
                float gi = g_sh[b][h], gf = g_sh[b][HH+h], gg = g_sh[b][2*HH+h], go = g_sh[b][3*HH+h];
                c1 = sig_ap(gf) * c1 + sig_ap(gi) * tanh_ap(gg);
                h_sh[b][h] = sig_ap(go) * tanh_ap(c1);
            }
            {
                int i = tid + 256, b = i >> 6, h = i & 63;            // b 4..5
                float gi = g_sh[b][h], gf = g_sh[b][HH+h], gg = g_sh[b][2*HH+h], go = g_sh[b][3*HH+h];
                c2 = sig_ap(gf) * c2 + sig_ap(gi) * tanh_ap(gg);
                h_sh[b][h] = sig_ap(go) * tanh_ap(c2);
            }
            if (tid < 64){
                int h = tid;                                          // b 6
                float gi = g_sh[6][h], gf = g_sh[6][HH+h], gg = g_sh[6][2*HH+h], go = g_sh[6][3*HH+h];
                c3 = sig_ap(gf) * c3 + sig_ap(gi) * tanh_ap(gg);
                h_sh[6][h] = sig_ap(go) * tanh_ap(c3);
            }
        }
        __syncthreads();
    }

    // ---- FC head: 28 outputs ----
    if (tid < NB * OO){
        const int b = tid >> 2, o = tid & 3;
        if ((bbase + b) < BB){
            float s = b_fc[o];
            #pragma unroll
            for (int k = 0; k < HH; k++)
                s = __fmaf_rn(W_fc[o*HH + k], h_sh[b][k], s);
            out[(size_t)(bbase + b) * OO + o] = s;
        }
    }
}

extern "C" void kernel_launch(void* const* d_in, const int* in_sizes, int n_in,
                              void* d_out, int out_size)
{
    const float* x    = (const float*)d_in[0];
    const float* W_ih = (const float*)d_in[1];
    const float* W_hh = (const float*)d_in[2];
    const float* b_ih = (const float*)d_in[3];
    const float* b_hh = (const float*)d_in[4];
    const float* W_fc = (const float*)d_in[5];
    const float* b_fc = (const float*)d_in[6];
    float* out = (float*)d_out;

    lstm_fused_kernel<<<GRID, NT>>>(x, W_ih, W_hh, b_ih, b_hh, W_fc, b_fc, out);
}

// round 11
// speedup vs baseline: 2.7435x; 2.3461x over previous
#include <cuda_runtime.h>
#include <cuda_fp16.h>

// Problem constants: B=2048, T=512, I=4, H=64, O=4
#define TT 512
#define BB 2048
#define HH 64
#define OO 4
#define NB 16    // batch rows per block = mma M tile (exact: 2048 = 128*16)
#define GRID 128
#define NT 256   // 8 warps; warp w owns gate-columns [32w, 32w+32)
#define HW 88    // h_sh row width in halfs: 0-63 h, 64-67 x, 68 bias-one, 69-87 zero
                 // stride 88 halfs = 44 words -> conflict-free fragment loads

__device__ __forceinline__ float tanh_ap(float x){
    float r; asm("tanh.approx.f32 %0, %1;" : "=f"(r) : "f"(x)); return r;
}
__device__ __forceinline__ float sig_ap(float x){
    return __fmaf_rn(0.5f, tanh_ap(0.5f * x), 0.5f);
}
__device__ __forceinline__ unsigned packh2(float lo, float hi){
    __half2 h = __floats2half2_rn(lo, hi);
    return *reinterpret_cast<unsigned*>(&h);
}
// D = A(16x16 f16, row) * B(16x8 f16, col) + D (f32)
__device__ __forceinline__ void mma16816(float* c, const unsigned* a, unsigned b0, unsigned b1){
    asm volatile(
        "mma.sync.aligned.m16n8k16.row.col.f32.f16.f16.f32 "
        "{%0,%1,%2,%3}, {%4,%5,%6,%7}, {%8,%9}, {%0,%1,%2,%3};\n"
        : "+f"(c[0]), "+f"(c[1]), "+f"(c[2]), "+f"(c[3])
        : "r"(a[0]), "r"(a[1]), "r"(a[2]), "r"(a[3]), "r"(b0), "r"(b1));
}

__global__ void __launch_bounds__(NT, 1) lstm_mma_kernel(
    const float* __restrict__ x,     // [B, T, I]
    const float* __restrict__ W_ih,  // [4H, I]
    const float* __restrict__ W_hh,  // [4H, H]
    const float* __restrict__ b_ih,  // [4H]
    const float* __restrict__ b_hh,  // [4H]
    const float* __restrict__ W_fc,  // [O, H]
    const float* __restrict__ b_fc,  // [O]
    float* __restrict__ out)         // [1, B, O]
{
    __shared__ __half h_hi[2][NB][HW];   // double-buffered augmented A matrix (hi part)
    __shared__ __half h_lo[2][NB][HW];   // lo (residual) part

    const int tid  = threadIdx.x;
    const int wid  = tid >> 5;
    const int lane = tid & 31;
    const int g    = lane >> 2;          // fragment group id (row / n-col selector)
    const int ti   = lane & 3;           // thread-in-group (k / c-col selector)
    const int bbase = blockIdx.x * NB;

    // Gate-column permutation: col -> W row. col = 4*u + {0:i,1:g,2:f,3:o}
    // PyTorch W rows: i:0-63, f:64-127, g:128-191, o:192-255.

    // ---- B fragments (stationary weights in registers): [nt 0..3][kt 0..4] ----
    unsigned bf0[4][5], bf1[4][5];
    #pragma unroll
    for (int nt = 0; nt < 4; nt++){
        int ncol = wid*32 + nt*8 + g;
        int u  = ncol >> 2;
        int gt = ncol & 3;
        int wrow = u + (gt == 0 ? 0 : gt == 1 ? 128 : gt == 2 ? 64 : 192);
        #pragma unroll
        for (int kt = 0; kt < 4; kt++){
            const float* wr = W_hh + (size_t)wrow * HH + kt*16;
            bf0[nt][kt] = packh2(wr[2*ti],     wr[2*ti + 1]);
            bf1[nt][kt] = packh2(wr[2*ti + 8], wr[2*ti + 9]);
        }
        // kt=4: rows 64-67 = W_ih, row 68 = bias, rows 69-79 = 0
        float e0 = 0.f, e1 = 0.f;
        if (ti < 2){ e0 = W_ih[wrow*4 + 2*ti]; e1 = W_ih[wrow*4 + 2*ti + 1]; }
        else if (ti == 2){ e0 = b_ih[wrow] + b_hh[wrow]; }
        bf0[nt][4] = packh2(e0, e1);
        bf1[nt][4] = 0u;
    }

    // ---- init shared: zero everything, set bias-one column, load x(t=0) ----
    for (int i = tid; i < 2*NB*HW; i += NT){
        ((__half*)h_hi)[i] = __float2half(0.f);
        ((__half*)h_lo)[i] = __float2half(0.f);
    }
    __syncthreads();
    if (tid < 2*NB){
        int p = tid >> 4, r = tid & 15;
        h_hi[p][r][68] = __float2half(1.f);   // bias-one (lo stays 0)
    }
    if (tid < NB){
        float4 xv = ((const float4*)x)[ (size_t)(bbase + tid) * TT ];
        float v[4] = {xv.x, xv.y, xv.z, xv.w};
        #pragma unroll
        for (int z = 0; z < 4; z++){
            __half hh = __float2half(v[z]);
            h_hi[0][tid][64 + z] = hh;
            h_lo[0][tid][64 + z] = __float2half(v[z] - __half2float(hh));
        }
    }
    __syncthreads();

    // cell state: meaningful on odd-ti lanes; [nt][slot] slot0=row g, slot1=row g+8
    float cst[4][2];
    #pragma unroll
    for (int nt = 0; nt < 4; nt++){ cst[nt][0] = 0.f; cst[nt][1] = 0.f; }

    const float cm = (ti & 1) ? 0.5f : 1.0f;   // act1: tanh (even: g-gate) / sigmoid (odd: o-gate)
    const float ca = (ti & 1) ? 0.5f : 0.0f;

    for (int t = 0; t < TT; t++){
        const int p = t & 1;

        // prefetch next x (global latency hidden under mma)
        float4 xn;
        const bool pre = (tid < NB) && (t + 1 < TT);
        if (pre) xn = ((const float4*)x)[ (size_t)(bbase + tid) * TT + (t + 1) ];

        // ---- A fragments (conflict-free LDS.32) ----
        unsigned ahi[5][4], alo[5][4];
        #pragma unroll
        for (int kt = 0; kt < 5; kt++){
            int cb = kt*16 + 2*ti;
            ahi[kt][0] = *(const unsigned*)&h_hi[p][g    ][cb];
            ahi[kt][1] = *(const unsigned*)&h_hi[p][g + 8][cb];
            ahi[kt][2] = *(const unsigned*)&h_hi[p][g    ][cb + 8];
            ahi[kt][3] = *(const unsigned*)&h_hi[p][g + 8][cb + 8];
            alo[kt][0] = *(const unsigned*)&h_lo[p][g    ][cb];
            alo[kt][1] = *(const unsigned*)&h_lo[p][g + 8][cb];
            alo[kt][2] = *(const unsigned*)&h_lo[p][g    ][cb + 8];
            alo[kt][3] = *(const unsigned*)&h_lo[p][g + 8][cb + 8];
        }

        // ---- gates = [h_hi + h_lo | x | 1] @ Waug^T  (fp32 accum) ----
        float C[4][4];
        #pragma unroll
        for (int nt = 0; nt < 4; nt++){
            C[nt][0] = 0.f; C[nt][1] = 0.f; C[nt][2] = 0.f; C[nt][3] = 0.f;
        }
        #pragma unroll
        for (int nt = 0; nt < 4; nt++){
            #pragma unroll
            for (int kt = 0; kt < 5; kt++){
                mma16816(C[nt], ahi[kt], bf0[nt][kt], bf1[nt][kt]);
                mma16816(C[nt], alo[kt], bf0[nt][kt], bf1[nt][kt]);
            }
        }

        // ---- epilogue: activations + lane-pair cell update + h writeback ----
        #pragma unroll
        for (int nt = 0; nt < 4; nt++){
            const int u = wid*8 + nt*2 + (ti >> 1);
            #pragma unroll
            for (int s = 0; s < 2; s++){
                float v0 = C[nt][2*s];          // i (even ti) / f (odd ti)
                float v1 = C[nt][2*s + 1];      // g (even ti) / o (odd ti)
                float a0 = sig_ap(v0);
                float a1 = __fmaf_rn(cm, tanh_ap(cm * v1), ca);
                float pp = a0 * a1;                               // sig(i)*tanh(g) on even
                float q  = __shfl_xor_sync(0xffffffffu, pp, 1);
                float cs = __fmaf_rn(a0, cst[nt][s], q);          // sig(f)*c + sig(i)tanh(g)
                cst[nt][s] = cs;
                float hv = a1 * tanh_ap(cs);                      // sig(o)*tanh(c)
                if (ti & 1){
                    int row = s ? (g + 8) : g;
                    __half hh = __float2half(hv);
                    h_hi[p ^ 1][row][u] = hh;
                    h_lo[p ^ 1][row][u] = __float2half(hv - __half2float(hh));
                }
            }
        }

        // stage next x into the buffer being written this step
        if (pre){
            float v[4] = {xn.x, xn.y, xn.z, xn.w};
            #pragma unroll
            for (int z = 0; z < 4; z++){
                __half hh = __float2half(v[z]);
                h_hi[p ^ 1][tid][64 + z] = hh;
                h_lo[p ^ 1][tid][64 + z] = __float2half(v[z] - __half2float(hh));
            }
        }
        __syncthreads();
    }

    // ---- FC head: final h in buffer 0 (TT even) ----
    if (tid < NB * OO){
        const int b = tid >> 2, o = tid & 3;
        float s = b_fc[o];
        #pragma unroll
        for (int k = 0; k < HH; k++){
            float hv = __half2float(h_hi[0][b][k]) + __half2float(h_lo[0][b][k]);
            s = __fmaf_rn(W_fc[o*HH + k], hv, s);
        }
        out[(size_t)(bbase + b) * OO + o] = s;
    }
}

extern "C" void kernel_launch(void* const* d_in, const int* in_sizes, int n_in,
                              void* d_out, int out_size)
{
    const float* x    = (const float*)d_in[0];
    const float* W_ih = (const float*)d_in[1];
    const float* W_hh = (const float*)d_in[2];
    const float* b_ih = (const float*)d_in[3];
    const float* b_hh = (const float*)d_in[4];
    const float* W_fc = (const float*)d_in[5];
    const float* b_fc = (const float*)d_in[6];
    float* out = (float*)d_out;

    lstm_mma_kernel<<<GRID, NT>>>(x, W_ih, W_hh, b_ih, b_hh, W_fc, b_fc, out);
}

// round 12
// speedup vs baseline: 4.2803x; 1.5602x over previous
#include <cuda_runtime.h>
#include <cuda_fp16.h>

// Problem constants: B=2048, T=512, I=4, H=64, O=4
#define TT 512
#define BB 2048
#define HH 64
#define OO 4
#define NB 16    // batch rows per block = mma M tile (exact: 2048 = 128*16)
#define GRID 128
#define NT 256   // 8 warps; warp w owns gate-columns [32w, 32w+32)
#define HW 88    // A row width in halfs: 0-63 h, 64-67 x, 68 bias-one, 69-87 zero
                 // stride 88 halfs -> ldmatrix phases hit 8 distinct banks

__device__ __forceinline__ float tanh_ap(float x){
    float r; asm("tanh.approx.f32 %0, %1;" : "=f"(r) : "f"(x)); return r;
}
__device__ __forceinline__ float sig_ap(float x){
    return __fmaf_rn(0.5f, tanh_ap(0.5f * x), 0.5f);
}
__device__ __forceinline__ unsigned packh2(float lo, float hi){
    __half2 h = __floats2half2_rn(lo, hi);
    return *reinterpret_cast<unsigned*>(&h);
}
// D = A(16x16 f16, row) * B(16x8 f16, col) + D (f32)
__device__ __forceinline__ void mma16816(float* c, const unsigned* a, unsigned b0, unsigned b1){
    asm volatile(
        "mma.sync.aligned.m16n8k16.row.col.f32.f16.f16.f32 "
        "{%0,%1,%2,%3}, {%4,%5,%6,%7}, {%8,%9}, {%0,%1,%2,%3};\n"
        : "+f"(c[0]), "+f"(c[1]), "+f"(c[2]), "+f"(c[3])
        : "r"(a[0]), "r"(a[1]), "r"(a[2]), "r"(a[3]), "r"(b0), "r"(b1));
}
__device__ __forceinline__ void ldsm_x4(unsigned &r0, unsigned &r1, unsigned &r2, unsigned &r3,
                                        unsigned addr){
    asm volatile("ldmatrix.sync.aligned.m8n8.x4.shared.b16 {%0,%1,%2,%3}, [%4];"
                 : "=r"(r0), "=r"(r1), "=r"(r2), "=r"(r3) : "r"(addr));
}
__device__ __forceinline__ unsigned smem_u32(const void* p){
    return (unsigned)__cvta_generic_to_shared(p);
}

__global__ void __launch_bounds__(NT, 1) lstm_mma_kernel(
    const float* __restrict__ x,     // [B, T, I]
    const float* __restrict__ W_ih,  // [4H, I]
    const float* __restrict__ W_hh,  // [4H, H]
    const float* __restrict__ b_ih,  // [4H]
    const float* __restrict__ b_hh,  // [4H]
    const float* __restrict__ W_fc,  // [O, H]
    const float* __restrict__ b_fc,  // [O]
    float* __restrict__ out)         // [1, B, O]
{
    __shared__ __half h_sh[2][NB][HW];   // double-buffered augmented A matrix (fp16)

    const int tid  = threadIdx.x;
    const int wid  = tid >> 5;
    const int lane = tid & 31;
    const int g    = lane >> 2;          // fragment group id
    const int ti   = lane & 3;           // thread-in-group
    const int bbase = blockIdx.x * NB;

    // Gate-column permutation: col = 4*u + {0:i,1:g,2:f,3:o}; W rows i:0-63 f:64-127 g:128-191 o:192-255
    // ---- B fragments (stationary weights in registers): [nt 0..3][kt 0..4] ----
    unsigned bf0[4][5], bf1[4][5];
    #pragma unroll
    for (int nt = 0; nt < 4; nt++){
        int ncol = wid*32 + nt*8 + g;
        int u  = ncol >> 2;
        int gt = ncol & 3;
        int wrow = u + (gt == 0 ? 0 : gt == 1 ? 128 : gt == 2 ? 64 : 192);
        #pragma unroll
        for (int kt = 0; kt < 4; kt++){
            const float* wr = W_hh + (size_t)wrow * HH + kt*16;
            bf0[nt][kt] = packh2(wr[2*ti],     wr[2*ti + 1]);
            bf1[nt][kt] = packh2(wr[2*ti + 8], wr[2*ti + 9]);
        }
        // kt=4: k rows 64-67 = W_ih, 68 = bias, 69-79 = 0
        float e0 = 0.f, e1 = 0.f;
        if (ti < 2){ e0 = W_ih[wrow*4 + 2*ti]; e1 = W_ih[wrow*4 + 2*ti + 1]; }
        else if (ti == 2){ e0 = b_ih[wrow] + b_hh[wrow]; }
        bf0[nt][4] = packh2(e0, e1);
        bf1[nt][4] = 0u;
    }

    // ---- ldmatrix per-lane source offsets (halfs) for the 4 8x8 tiles ----
    const int lrow = (lane & 7) + ((lane >> 3) & 1) * 8;   // m0/m2: rows 0-7, m1/m3: 8-15
    const int lcol = (lane >> 4) << 3;                     // m2/m3: +8 cols
    const unsigned abase0 = smem_u32(&h_sh[0][lrow][lcol]);
    const unsigned abase1 = smem_u32(&h_sh[1][lrow][lcol]);

    // ---- init shared: zero both buffers, bias-one col, x(t=0) ----
    for (int i = tid; i < 2*NB*HW; i += NT) ((__half*)h_sh)[i] = __float2half(0.f);
    __syncthreads();
    if (tid < 2*NB){
        int p = tid >> 4, r = tid & 15;
        h_sh[p][r][68] = __float2half(1.f);
    }
    if (tid < NB){
        float4 xv = ((const float4*)x)[ (size_t)(bbase + tid) * TT ];
        h_sh[0][tid][64] = __float2half(xv.x);
        h_sh[0][tid][65] = __float2half(xv.y);
        h_sh[0][tid][66] = __float2half(xv.z);
        h_sh[0][tid][67] = __float2half(xv.w);
    }
    __syncthreads();

    // cell state: meaningful on odd-ti lanes; [nt][slot] slot0=row g, slot1=row g+8
    float cst[4][2];
    #pragma unroll
    for (int nt = 0; nt < 4; nt++){ cst[nt][0] = 0.f; cst[nt][1] = 0.f; }

    const float cm = (ti & 1) ? 0.5f : 1.0f;   // act1: tanh (even ti: g) / sigmoid (odd ti: o)
    const float ca = (ti & 1) ? 0.5f : 0.0f;

    for (int t = 0; t < TT; t++){
        const int p = t & 1;
        const unsigned abase = p ? abase1 : abase0;

        // prefetch next x (global latency hidden under mma)
        float4 xn;
        const bool pre = (tid < NB) && (t + 1 < TT);
        if (pre) xn = ((const float4*)x)[ (size_t)(bbase + tid) * TT + (t + 1) ];

        // ---- A fragments via ldmatrix.x4 (5 instructions) ----
        unsigned af[5][4];
        #pragma unroll
        for (int kt = 0; kt < 5; kt++)
            ldsm_x4(af[kt][0], af[kt][1], af[kt][2], af[kt][3], abase + kt*32);

        // ---- gates = [h | x | 1] @ Waug^T (fp32 accum, 4 independent chains) ----
        float C[4][4];
        #pragma unroll
        for (int nt = 0; nt < 4; nt++){
            C[nt][0] = 0.f; C[nt][1] = 0.f; C[nt][2] = 0.f; C[nt][3] = 0.f;
        }
        #pragma unroll
        for (int kt = 0; kt < 5; kt++){
            #pragma unroll
            for (int nt = 0; nt < 4; nt++)
                mma16816(C[nt], af[kt], bf0[nt][kt], bf1[nt][kt]);
        }

        // ---- epilogue: activations + lane-pair cell update + h writeback ----
        #pragma unroll
        for (int nt = 0; nt < 4; nt++){
            const int u = wid*8 + nt*2 + (ti >> 1);
            #pragma unroll
            for (int s = 0; s < 2; s++){
                float v0 = C[nt][2*s];          // i (even ti) / f (odd ti)
                float v1 = C[nt][2*s + 1];      // g (even ti) / o (odd ti)
                float a0 = sig_ap(v0);
                float a1 = __fmaf_rn(cm, tanh_ap(cm * v1), ca);
                float pp = a0 * a1;                               // sig(i)*tanh(g) on even
                float q  = __shfl_xor_sync(0xffffffffu, pp, 1);
                float cs = __fmaf_rn(a0, cst[nt][s], q);          // sig(f)*c + sig(i)tanh(g)
                cst[nt][s] = cs;
                float hv = a1 * tanh_ap(cs);                      // sig(o)*tanh(c)
                if (ti & 1){
                    int row = s ? (g + 8) : g;
                    h_sh[p ^ 1][row][u] = __float2half(hv);
                }
            }
        }

        // stage next x into the buffer being written this step
        if (pre){
            h_sh[p ^ 1][tid][64] = __float2half(xn.x);
            h_sh[p ^ 1][tid][65] = __float2half(xn.y);
            h_sh[p ^ 1][tid][66] = __float2half(xn.z);
            h_sh[p ^ 1][tid][67] = __float2half(xn.w);
        }
        __syncthreads();
    }

    // ---- FC head: final h in buffer 0 (TT even) ----
    if (tid < NB * OO){
        const int b = tid >> 2, o = tid & 3;
        float s = b_fc[o];
        #pragma unroll
        for (int k = 0; k < HH; k++)
            s = __fmaf_rn(W_fc[o*HH + k], __half2float(h_sh[0][b][k]), s);
        out[(size_t)(bbase + b) * OO + o] = s;
    }
}

extern "C" void kernel_launch(void* const* d_in, const int* in_sizes, int n_in,
                              void* d_out, int out_size)
{
    const float* x    = (const float*)d_in[0];
    const float* W_ih = (const float*)d_in[1];
    const float* W_hh = (const float*)d_in[2];
    const float* b_ih = (const float*)d_in[3];
    const float* b_hh = (const float*)d_in[4];
    const float* W_fc = (const float*)d_in[5];
    const float* b_fc = (const float*)d_in[6];
    float* out = (float*)d_out;

    lstm_mma_kernel<<<GRID, NT>>>(x, W_ih, W_hh, b_ih, b_hh, W_fc, b_fc, out);
}